// round 10
// baseline (speedup 1.0000x reference)
#include <cuda_runtime.h>

#define TT    512
#define BSZ   256
#define DIN   64
#define HH    128
#define BPC   8
#define NGRP  32
#define NTHR  512
#define RPC   256        // rows per CTA: 4 gates x 64 units
#define UPC   64         // units per CTA
#define NB0   48         // k-blocks layer0 (K=192)
#define NB1   64         // k-blocks layer1 (K=256)
#define NB0H  24         // k-blocks per segment, layer0
#define NB1H  32         // k-blocks per segment, layer1
#define SKB   24         // smem-resident k-blocks per segment
#define GKB1  (NB1H-SKB) // 8 gmem k-blocks per segment (layer1 only)
#define NCTA  (NGRP*4)   // 128
#define DYNSMEM (2*SKB*RPC*16)   // 196608 B = 192 KB

// Blocked weights per (half, kb, row): float4 = W[grow][4kb..4kb+3]
__device__ float4 g_W0B[2 * NB0 * RPC];
__device__ float4 g_W1B[2 * NB1 * RPC];
// Whole-h handoff buffers (full sequence, no wrap) + flags
__device__ float g_h0[TT][NGRP][2][BPC][UPC];
__device__ float g_h1[TT][NGRP][2][BPC][UPC];
__device__ int   g_f0[TT][NGRP][2];
__device__ int   g_f1[TT][NGRP][2];

__global__ void prep_kernel(const float* __restrict__ Wih0,
                            const float* __restrict__ Whh0,
                            const float* __restrict__ Wih1,
                            const float* __restrict__ Whh1)
{
    int idx = blockIdx.x * blockDim.x + threadIdx.x;
    int stride = gridDim.x * blockDim.x;
    for (int e = idx; e < TT * NGRP * 2; e += stride) {
        ((int*)g_f0)[e] = 0;
        ((int*)g_f1)[e] = 0;
    }
    for (int e = idx; e < 2 * NB0 * RPC * 4; e += stride) {
        int i = e & 3, e2 = e >> 2;
        int r = e2 % RPC, e3 = e2 / RPC;
        int kb = e3 % NB0, half = e3 / NB0;
        int k = kb * 4 + i;
        int gate = r >> 6, ul = r & 63;
        int grow = gate * HH + half * UPC + ul;
        float v = (k < DIN) ? Wih0[grow * DIN + k] : Whh0[grow * HH + (k - DIN)];
        ((float*)g_W0B)[e] = v;
    }
    for (int e = idx; e < 2 * NB1 * RPC * 4; e += stride) {
        int i = e & 3, e2 = e >> 2;
        int r = e2 % RPC, e3 = e2 / RPC;
        int kb = e3 % NB1, half = e3 / NB1;
        int k = kb * 4 + i;
        int gate = r >> 6, ul = r & 63;
        int grow = gate * HH + half * UPC + ul;
        float v = (k < HH) ? Wih1[grow * HH + k] : Whh1[grow * HH + (k - HH)];
        ((float*)g_W1B)[e] = v;
    }
}

__device__ __forceinline__ void fma2(unsigned long long& d,
                                     unsigned long long a,
                                     unsigned long long b)
{
    asm("fma.rn.f32x2 %0, %1, %2, %0;" : "+l"(d) : "l"(a), "l"(b));
}
__device__ __forceinline__ float flo(unsigned long long v) {
    return __uint_as_float((unsigned)(v & 0xffffffffu));
}
__device__ __forceinline__ float fhi(unsigned long long v) {
    return __uint_as_float((unsigned)(v >> 32));
}
__device__ __forceinline__ float sigf(float x) {
    return __fdividef(1.0f, 1.0f + __expf(-x));
}
__device__ __forceinline__ float tanhfast(float x) {
    return 1.0f - __fdividef(2.0f, __expf(2.0f * x) + 1.0f);
}
__device__ __forceinline__ int ld_acq(const int* p) {
    int v;
    asm volatile("ld.acquire.gpu.global.s32 %0, [%1];" : "=r"(v) : "l"(p) : "memory");
    return v;
}
__device__ __forceinline__ void st_rel(int* p, int v) {
    asm volatile("st.release.gpu.global.s32 [%0], %1;" :: "l"(p), "r"(v) : "memory");
}
__device__ __forceinline__ float4 ldcg4(const float4* p) {
    float4 v;
    asm volatile("ld.global.cg.v4.f32 {%0,%1,%2,%3}, [%4];"
                 : "=f"(v.x), "=f"(v.y), "=f"(v.z), "=f"(v.w) : "l"(p) : "memory");
    return v;
}
__device__ __forceinline__ float ldcg(const float* p) {
    float v;
    asm volatile("ld.global.cg.f32 %0, [%1];" : "=f"(v) : "l"(p) : "memory");
    return v;
}
__device__ __forceinline__ ulonglong2 ldcg_u2(const ulonglong2* p) {
    ulonglong2 v;
    asm volatile("ld.global.cg.v2.u64 {%0,%1}, [%2];"
                 : "=l"(v.x), "=l"(v.y) : "l"(p) : "memory");
    return v;
}
__device__ __forceinline__ void stcg(float* p, float v) {
    asm volatile("st.global.cg.f32 [%0], %1;" :: "l"(p), "f"(v) : "memory");
}

__global__ void __launch_bounds__(NTHR, 1)
lstm_kernel(const float* __restrict__ state,
            const float* __restrict__ b_ih0, const float* __restrict__ b_hh0,
            const float* __restrict__ b_ih1, const float* __restrict__ b_hh1,
            const float* __restrict__ W_out, const float* __restrict__ b_out,
            float* __restrict__ out)
{
    // dynamic smem: resident weights, [seg*SKB + kbl][r] as 16B blocks
    extern __shared__ __align__(16) unsigned long long dynw[];
    ulonglong2* ws = (ulonglong2*)dynw;

    __shared__ __align__(16) float sx[2][BPC][192];  // L0 buf / L1 flat rows(256)
    __shared__ float sg[BPC][2][RPC];                 // k-seg partial pre-acts
    __shared__ float swout[HH];
    __shared__ float sbout;

    const int grp  = blockIdx.x >> 2;
    const int role = blockIdx.x & 3;    // 0,1 = L0 halves; 2,3 = L1 halves
    const int gb   = grp * BPC;
    const int tid  = threadIdx.x;
    const int seg  = tid >> 8;          // k-segment 0/1 (dot phase)
    const int r    = tid & 255;         // CTA-local row (gate*64 + unit)
    const int ua   = tid & 63;          // act-phase local unit
    const int ba   = (tid >> 6) & 7;    // act-phase batch

    if (role < 2) {
        // ==================== L0 half-CTA (all weights in smem) ====================
        const int half = role, peer = half ^ 1;
        // copy weights: L0 kb 0..47 contiguous -> ws (2*SKB*RPC blocks)
        {
            const ulonglong2* src = (const ulonglong2*)g_W0B + (size_t)half * NB0 * RPC;
            for (int e = tid; e < NB0 * RPC; e += NTHR)
                ws[e] = ldcg_u2(src + e);
        }
        const int gr0 = half * UPC + ua;
        const float bi = b_ih0[gr0]          + b_hh0[gr0];
        const float bf = b_ih0[HH + gr0]     + b_hh0[HH + gr0];
        const float bg = b_ih0[2*HH + gr0]   + b_hh0[2*HH + gr0];
        const float bo = b_ih0[3*HH + gr0]   + b_hh0[3*HH + gr0];
        for (int i2 = tid; i2 < 2 * BPC * HH; i2 += NTHR) {
            int pq = i2 / (BPC * HH), rem = i2 % (BPC * HH);
            sx[pq][rem / HH][DIN + (rem % HH)] = 0.0f;   // h0(-1) = 0
        }
        sx[0][ba][ua] = ldcg(state + (gb + ba) * DIN + ua);   // x(0)
        float cst = 0.0f;
        const ulonglong2* wsb = ws + (size_t)seg * NB0H * RPC + r;
        __syncthreads();

        for (int t = 0; t < TT; ++t) {
            const int q = t & 1;
            if (t > 0) {
                if (tid == 0)
                    while (ld_acq(&g_f0[t - 1][grp][peer]) == 0) { }
                __syncthreads();
                if (tid < 128) {   // copy peer h0-half(t-1)
                    int b = tid >> 4, q4 = tid & 15;
                    ((float4*)&sx[q][b][DIN + peer * UPC])[q4] =
                        ldcg4((const float4*)&g_h0[t - 1][grp][peer][b][0] + q4);
                }
            }
            if (t + 1 < TT)       // prefetch x(t+1)
                sx[q ^ 1][ba][ua] =
                    ldcg(state + ((size_t)(t + 1) * BSZ + gb + ba) * DIN + ua);
            __syncthreads();

            {   // dot: smem weights only
                unsigned long long acc[BPC];
                #pragma unroll
                for (int b = 0; b < BPC; ++b) acc[b] = 0ull;
                const float* xb = &sx[q][0][0];
                #pragma unroll 4
                for (int kbl = 0; kbl < NB0H; ++kbl) {
                    ulonglong2 w = wsb[(size_t)kbl * RPC];
                    #pragma unroll
                    for (int b = 0; b < BPC; ++b) {
                        ulonglong2 xv =
                            ((const ulonglong2*)(xb + (size_t)b * 192))[seg * NB0H + kbl];
                        fma2(acc[b], w.x, xv.x);
                        fma2(acc[b], w.y, xv.y);
                    }
                }
                #pragma unroll
                for (int b = 0; b < BPC; ++b)
                    sg[b][seg][r] = flo(acc[b]) + fhi(acc[b]);
            }
            __syncthreads();

            {   // act: thread = (unit ua, batch ba)
                float p0 = sg[ba][0][ua]         + sg[ba][1][ua]         + bi;
                float p1 = sg[ba][0][UPC+ua]     + sg[ba][1][UPC+ua]     + bf;
                float p2 = sg[ba][0][2*UPC+ua]   + sg[ba][1][2*UPC+ua]   + bg;
                float p3 = sg[ba][0][3*UPC+ua]   + sg[ba][1][3*UPC+ua]   + bo;
                float gi = sigf(p0), gf = sigf(p1);
                float gG = tanhfast(p2), go = sigf(p3);
                cst = gf * cst + gi * gG;
                float h = go * tanhfast(cst);
                sx[q ^ 1][ba][DIN + half * UPC + ua] = h;    // own recurrence
                stcg(&g_h0[t][grp][half][ba][ua], h);        // publish
            }
            __threadfence();
            __syncthreads();
            if (tid == 0) st_rel(&g_f0[t][grp][half], 1);
        }
    } else {
        // ==================== L1 half-CTA (24/32 kb per seg in smem) ====================
        const int half = role - 2, peer = half ^ 1;
        float* sxb = &sx[0][0][0];           // rows of 256 floats
        // copy weights: per seg, local kb [0,SKB) -> smem
        {
            const ulonglong2* src = (const ulonglong2*)g_W1B + (size_t)half * NB1 * RPC;
            for (int e = tid; e < 2 * SKB * RPC; e += NTHR) {
                int s24 = e >> 8, rr = e & 255;
                int sseg = s24 / SKB, kbl = s24 % SKB;
                ws[e] = ldcg_u2(src + ((size_t)(sseg * NB1H + kbl) * RPC + rr));
            }
        }
        const int gr0 = half * UPC + ua;
        const float bi = b_ih1[gr0]          + b_hh1[gr0];
        const float bf = b_ih1[HH + gr0]     + b_hh1[HH + gr0];
        const float bg = b_ih1[2*HH + gr0]   + b_hh1[2*HH + gr0];
        const float bo = b_ih1[3*HH + gr0]   + b_hh1[3*HH + gr0];
        if (tid < HH) swout[tid] = W_out[tid];
        if (tid == 0) sbout = b_out[0];
        for (int i2 = tid; i2 < BPC * HH; i2 += NTHR)
            sxb[(i2 >> 7) * 256 + HH + (i2 & 127)] = 0.0f;   // h1(-1) = 0
        float cst = 0.0f;
        const ulonglong2* wsb = ws + (size_t)seg * SKB * RPC + r;
        const ulonglong2* wgb = (const ulonglong2*)g_W1B
                              + ((size_t)(half * NB1 + seg * NB1H + SKB) * RPC + r);
        __syncthreads();

        for (int t = 0; t < TT; ++t) {
            if (tid == 0) {
                while (ld_acq(&g_f0[t][grp][0]) == 0) { }
                while (ld_acq(&g_f0[t][grp][1]) == 0) { }
                if (t > 0) while (ld_acq(&g_f1[t - 1][grp][peer]) == 0) { }
            }
            __syncthreads();
            if (tid < 256) {   // copy full h0(t)
                int b = tid >> 5, q4 = tid & 31;
                int hh = q4 >> 4, qq = q4 & 15;
                ((float4*)&sxb[b * 256 + hh * UPC])[qq] =
                    ldcg4((const float4*)&g_h0[t][grp][hh][b][0] + qq);
            } else if (t > 0 && tid < 384) {   // copy peer h1-half(t-1)
                int idx = tid - 256;
                int b = idx >> 4, qq = idx & 15;
                ((float4*)&sxb[b * 256 + HH + peer * UPC])[qq] =
                    ldcg4((const float4*)&g_h1[t - 1][grp][peer][b][0] + qq);
            }
            __syncthreads();

            // head: out(t-1) from assembled full h1(t-1) (half-0 CTA only)
            if (half == 0 && t > 0 && tid < 64) {
                int b = tid >> 3, ch = tid & 7;
                float p = 0.0f;
                #pragma unroll
                for (int m = 0; m < 16; ++m) {
                    int u = ch * 16 + m;
                    p += sxb[b * 256 + HH + u] * swout[u];
                }
                p += __shfl_down_sync(0xffffffffu, p, 4, 8);
                p += __shfl_down_sync(0xffffffffu, p, 2, 8);
                p += __shfl_down_sync(0xffffffffu, p, 1, 8);
                if (ch == 0) out[(size_t)(t - 1) * BSZ + gb + b] = p + sbout;
            }

            {   // dot: smem part (SKB kb) + gmem tail (GKB1 kb)
                unsigned long long acc[BPC];
                #pragma unroll
                for (int b = 0; b < BPC; ++b) acc[b] = 0ull;
                #pragma unroll 4
                for (int kbl = 0; kbl < SKB; ++kbl) {
                    ulonglong2 w = wsb[(size_t)kbl * RPC];
                    #pragma unroll
                    for (int b = 0; b < BPC; ++b) {
                        ulonglong2 xv =
                            ((const ulonglong2*)(sxb + (size_t)b * 256))[seg * NB1H + kbl];
                        fma2(acc[b], w.x, xv.x);
                        fma2(acc[b], w.y, xv.y);
                    }
                }
                #pragma unroll
                for (int kbl = 0; kbl < GKB1; ++kbl) {
                    ulonglong2 w = ldcg_u2(wgb + (size_t)kbl * RPC);
                    #pragma unroll
                    for (int b = 0; b < BPC; ++b) {
                        ulonglong2 xv =
                            ((const ulonglong2*)(sxb + (size_t)b * 256))[seg * NB1H + SKB + kbl];
                        fma2(acc[b], w.x, xv.x);
                        fma2(acc[b], w.y, xv.y);
                    }
                }
                #pragma unroll
                for (int b = 0; b < BPC; ++b)
                    sg[b][seg][r] = flo(acc[b]) + fhi(acc[b]);
            }
            __syncthreads();

            {   // act
                float p0 = sg[ba][0][ua]         + sg[ba][1][ua]         + bi;
                float p1 = sg[ba][0][UPC+ua]     + sg[ba][1][UPC+ua]     + bf;
                float p2 = sg[ba][0][2*UPC+ua]   + sg[ba][1][2*UPC+ua]   + bg;
                float p3 = sg[ba][0][3*UPC+ua]   + sg[ba][1][3*UPC+ua]   + bo;
                float gi = sigf(p0), gf = sigf(p1);
                float gG = tanhfast(p2), go = sigf(p3);
                cst = gf * cst + gi * gG;
                float h = go * tanhfast(cst);
                sxb[ba * 256 + HH + half * UPC + ua] = h;    // own recurrence
                stcg(&g_h1[t][grp][half][ba][ua], h);        // publish
            }
            __threadfence();
            __syncthreads();
            if (tid == 0) st_rel(&g_f1[t][grp][half], 1);
        }

        // epilogue: out(TT-1) on half-0 CTA
        if (half == 0) {
            if (tid == 0)
                while (ld_acq(&g_f1[TT - 1][grp][1]) == 0) { }
            __syncthreads();
            if (tid < 128) {
                int b = tid >> 4, qq = tid & 15;
                ((float4*)&sxb[b * 256 + HH + UPC])[qq] =
                    ldcg4((const float4*)&g_h1[TT - 1][grp][1][b][0] + qq);
            }
            __syncthreads();
            if (tid < 64) {
                int b = tid >> 3, ch = tid & 7;
                float p = 0.0f;
                #pragma unroll
                for (int m = 0; m < 16; ++m) {
                    int u = ch * 16 + m;
                    p += sxb[b * 256 + HH + u] * swout[u];
                }
                p += __shfl_down_sync(0xffffffffu, p, 4, 8);
                p += __shfl_down_sync(0xffffffffu, p, 2, 8);
                p += __shfl_down_sync(0xffffffffu, p, 1, 8);
                if (ch == 0) out[(size_t)(TT - 1) * BSZ + gb + b] = p + sbout;
            }
        }
    }
}

extern "C" void kernel_launch(void* const* d_in, const int* in_sizes, int n_in,
                              void* d_out, int out_size)
{
    const float* state = (const float*)d_in[0];
    const float* W_ih0 = (const float*)d_in[1];
    const float* W_hh0 = (const float*)d_in[2];
    const float* b_ih0 = (const float*)d_in[3];
    const float* b_hh0 = (const float*)d_in[4];
    const float* W_ih1 = (const float*)d_in[5];
    const float* W_hh1 = (const float*)d_in[6];
    const float* b_ih1 = (const float*)d_in[7];
    const float* b_hh1 = (const float*)d_in[8];
    const float* W_out = (const float*)d_in[9];
    const float* b_out = (const float*)d_in[10];
    float* out = (float*)d_out;

    cudaFuncSetAttribute(lstm_kernel,
                         cudaFuncAttributeMaxDynamicSharedMemorySize, DYNSMEM);
    prep_kernel<<<224, 512>>>(W_ih0, W_hh0, W_ih1, W_hh1);
    lstm_kernel<<<NCTA, NTHR, DYNSMEM>>>(state, b_ih0, b_hh0, b_ih1, b_hh1,
                                         W_out, b_out, out);
}

// round 11
// speedup vs baseline: 1.0897x; 1.0897x over previous
#include <cuda_runtime.h>

#define TT    512
#define BSZ   256
#define DIN   64
#define HH    128
#define BPC   8
#define NGRP  32
#define NTHR  512
#define RPC   256        // rows per CTA: 4 gates x 64 units
#define UPC   64
#define NB0   48         // k-blocks layer0 (K=192)
#define NB1   64         // k-blocks layer1 (K=256)
#define NB0H  24         // per k-segment
#define NB1H  32
#define SKB   24         // smem-resident kb per segment (layer1)
#define GKB1  (NB1H-SKB) // 8 gmem kb per segment (layer1)
#define NCTA  (NGRP*4)   // 128
#define DYNSMEM (NB0*RPC*16)   // 196608 B = 192 KB

// Blocked weights per (half, kb, row): float4 = W[grow][4kb..4kb+3]
__device__ float4 g_W0B[2 * NB0 * RPC];
__device__ float4 g_W1B[2 * NB1 * RPC];

__global__ void prep_kernel(const float* __restrict__ Wih0,
                            const float* __restrict__ Whh0,
                            const float* __restrict__ Wih1,
                            const float* __restrict__ Whh1)
{
    int idx = blockIdx.x * blockDim.x + threadIdx.x;
    int stride = gridDim.x * blockDim.x;
    for (int e = idx; e < 2 * NB0 * RPC * 4; e += stride) {
        int i = e & 3, e2 = e >> 2;
        int r = e2 % RPC, e3 = e2 / RPC;
        int kb = e3 % NB0, half = e3 / NB0;
        int k = kb * 4 + i;
        int gate = r >> 6, ul = r & 63;
        int grow = gate * HH + half * UPC + ul;
        float v = (k < DIN) ? Wih0[grow * DIN + k] : Whh0[grow * HH + (k - DIN)];
        ((float*)g_W0B)[e] = v;
    }
    for (int e = idx; e < 2 * NB1 * RPC * 4; e += stride) {
        int i = e & 3, e2 = e >> 2;
        int r = e2 % RPC, e3 = e2 / RPC;
        int kb = e3 % NB1, half = e3 / NB1;
        int k = kb * 4 + i;
        int gate = r >> 6, ul = r & 63;
        int grow = gate * HH + half * UPC + ul;
        float v = (k < HH) ? Wih1[grow * HH + k] : Whh1[grow * HH + (k - HH)];
        ((float*)g_W1B)[e] = v;
    }
}

__device__ __forceinline__ void fma2(unsigned long long& d,
                                     unsigned long long a,
                                     unsigned long long b)
{
    asm("fma.rn.f32x2 %0, %1, %2, %0;" : "+l"(d) : "l"(a), "l"(b));
}
__device__ __forceinline__ float flo(unsigned long long v) {
    return __uint_as_float((unsigned)(v & 0xffffffffu));
}
__device__ __forceinline__ float fhi(unsigned long long v) {
    return __uint_as_float((unsigned)(v >> 32));
}
__device__ __forceinline__ float sigf(float x) {
    return __fdividef(1.0f, 1.0f + __expf(-x));
}
__device__ __forceinline__ float tanhfast(float x) {
    return 1.0f - __fdividef(2.0f, __expf(2.0f * x) + 1.0f);
}
__device__ __forceinline__ float ldcg(const float* p) {
    float v;
    asm volatile("ld.global.cg.f32 %0, [%1];" : "=f"(v) : "l"(p) : "memory");
    return v;
}
__device__ __forceinline__ ulonglong2 ldcg_u2(const ulonglong2* p) {
    ulonglong2 v;
    asm volatile("ld.global.cg.v2.u64 {%0,%1}, [%2];"
                 : "=l"(v.x), "=l"(v.y) : "l"(p) : "memory");
    return v;
}
__device__ __forceinline__ unsigned smem_u32(const void* p) {
    unsigned a;
    asm("{ .reg .u64 t; cvta.to.shared.u64 t, %1; cvt.u32.u64 %0, t; }"
        : "=r"(a) : "l"(p));
    return a;
}
__device__ __forceinline__ unsigned cta_rank() {
    unsigned r;
    asm("mov.u32 %0, %%cluster_ctarank;" : "=r"(r));
    return r;
}
__device__ __forceinline__ unsigned mapa_u32(unsigned a, unsigned rank) {
    unsigned r;
    asm("mapa.shared::cluster.u32 %0, %1, %2;" : "=r"(r) : "r"(a), "r"(rank));
    return r;
}
__device__ __forceinline__ void mbar_init(unsigned a, unsigned cnt) {
    asm volatile("mbarrier.init.shared.b64 [%0], %1;" :: "r"(a), "r"(cnt) : "memory");
}
__device__ __forceinline__ void mbar_arrive_rk(unsigned local_a, unsigned rank) {
    unsigned ra = mapa_u32(local_a, rank);
    asm volatile("mbarrier.arrive.release.cluster.shared::cluster.b64 _, [%0];"
                 :: "r"(ra) : "memory");
}
__device__ __forceinline__ void mbar_wait(unsigned a, unsigned parity) {
    asm volatile(
        "{\n\t.reg .pred P;\n\t"
        "W_%=:\n\t"
        "mbarrier.try_wait.parity.acquire.cluster.shared::cta.b64 P, [%0], %1, 0x989680;\n\t"
        "@P bra D_%=;\n\t"
        "bra W_%=;\n\t"
        "D_%=:\n\t}"
        :: "r"(a), "r"(parity) : "memory");
}
__device__ __forceinline__ void st_dsmem(unsigned local_a, unsigned rank, float v) {
    unsigned ra = mapa_u32(local_a, rank);
    asm volatile("st.shared::cluster.f32 [%0], %1;" :: "r"(ra), "f"(v) : "memory");
}
#define CLUSTER_SYNC() do { \
    asm volatile("barrier.cluster.arrive.aligned;" ::: "memory"); \
    asm volatile("barrier.cluster.wait.aligned;" ::: "memory"); \
} while (0)

__global__ void __launch_bounds__(NTHR, 1) __cluster_dims__(4, 1, 1)
lstm_kernel(const float* __restrict__ state,
            const float* __restrict__ b_ih0, const float* __restrict__ b_hh0,
            const float* __restrict__ b_ih1, const float* __restrict__ b_hh1,
            const float* __restrict__ W_out, const float* __restrict__ b_out,
            float* __restrict__ out)
{
    extern __shared__ __align__(16) unsigned long long dynw[];
    ulonglong2* ws = (ulonglong2*)dynw;

    // Unified double-buffered input vectors, rows of 256 floats.
    //   L0 rows: [x(64) | h0(128) | pad]   L1 rows: [h0(128) | h1(128)]
    __shared__ __align__(16) float ubuf[2][BPC][256];
    __shared__ float sg[BPC][2][RPC];      // per-segment partial pre-acts
    __shared__ float swout[HH];
    __shared__ float sbout;
    __shared__ __align__(8) unsigned long long mbar[4];
    // rank<2 : mbar[0..1]=full peer-h0 in (cnt1), mbar[2..3]=empty-from-L1 (cnt2)
    // rank>=2: mbar[0..1]=full h0 in (cnt2),      mbar[2..3]=full peer-h1 in (cnt1)

    const int grp  = blockIdx.x >> 2;
    const int gb   = grp * BPC;
    const unsigned rank = cta_rank();
    const int tid  = threadIdx.x;
    const int seg  = tid >> 8;          // k-segment 0/1 (dot phase)
    const int r    = tid & 255;         // CTA-local row
    const int ua   = tid & 63;          // act-phase local unit
    const int ba   = tid >> 6;          // act-phase batch 0..7

    const unsigned mb0 = smem_u32(&mbar[0]);

    if (tid == 0) {
        if (rank < 2) {
            mbar_init(mb0 + 0,  1); mbar_init(mb0 + 8,  1);
            mbar_init(mb0 + 16, 2); mbar_init(mb0 + 24, 2);
        } else {
            mbar_init(mb0 + 0,  2); mbar_init(mb0 + 8,  2);
            mbar_init(mb0 + 16, 1); mbar_init(mb0 + 24, 1);
        }
    }

    if (rank < 2) {
        // ===================== L0 half-CTA =====================
        const int half = rank, peer = half ^ 1;
        // weights: all 48 kb resident in smem
        {
            const ulonglong2* src = (const ulonglong2*)g_W0B + (size_t)half * NB0 * RPC;
            for (int e = tid; e < NB0 * RPC; e += NTHR) ws[e] = ldcg_u2(src + e);
        }
        const int gr0 = half * UPC + ua;
        const float bi = b_ih0[gr0]        + b_hh0[gr0];
        const float bf = b_ih0[HH+gr0]     + b_hh0[HH+gr0];
        const float bg = b_ih0[2*HH+gr0]   + b_hh0[2*HH+gr0];
        const float bo = b_ih0[3*HH+gr0]   + b_hh0[3*HH+gr0];
        ubuf[0][ba][DIN + ua]      = 0.0f;         // h0(-1) = 0 (both halves)
        ubuf[0][ba][DIN + 64 + ua] = 0.0f;
        ubuf[0][ba][ua] = ldcg(state + (gb + ba) * DIN + ua);   // x(0)
        float cst = 0.0f;
        int phF[2] = {0, 0}, phE[2] = {0, 0};
        const ulonglong2* wsb = ws + (size_t)seg * NB0H * RPC + r;
        __syncthreads();
        CLUSTER_SYNC();

        for (int t = 0; t < TT; ++t) {
            const int q = t & 1;
            float xr = 0.0f;
            if (t + 1 < TT)
                xr = ldcg(state + ((size_t)(t + 1) * BSZ + gb + ba) * DIN + ua);
            if (tid == 0) {
                if (t > 0)  mbar_wait(mb0 + (unsigned)q * 8,      (unsigned)phF[q]);
                if (t >= 2) mbar_wait(mb0 + 16 + (unsigned)q * 8, (unsigned)phE[q]);
            }
            if (t > 0)  phF[q] ^= 1;
            if (t >= 2) phE[q] ^= 1;
            __syncthreads();   // B1: inputs for slot q complete
            ubuf[q ^ 1][ba][ua] = xr;   // x(t+1) into next slot

            {   // dot over slot q: [x | h0], kb = seg*24 .. +24
                unsigned long long acc[BPC];
                #pragma unroll
                for (int b = 0; b < BPC; ++b) acc[b] = 0ull;
                const float* xb = &ubuf[q][0][0];
                #pragma unroll 4
                for (int kbl = 0; kbl < NB0H; ++kbl) {
                    ulonglong2 w = wsb[(size_t)kbl * RPC];
                    #pragma unroll
                    for (int b = 0; b < BPC; ++b) {
                        ulonglong2 xv =
                            ((const ulonglong2*)(xb + (size_t)b * 256))[seg * NB0H + kbl];
                        fma2(acc[b], w.x, xv.x);
                        fma2(acc[b], w.y, xv.y);
                    }
                }
                #pragma unroll
                for (int b = 0; b < BPC; ++b)
                    sg[b][seg][r] = flo(acc[b]) + fhi(acc[b]);
            }
            __syncthreads();   // B2

            {   // act
                float p0 = sg[ba][0][ua]         + sg[ba][1][ua]         + bi;
                float p1 = sg[ba][0][UPC+ua]     + sg[ba][1][UPC+ua]     + bf;
                float p2 = sg[ba][0][2*UPC+ua]   + sg[ba][1][2*UPC+ua]   + bg;
                float p3 = sg[ba][0][3*UPC+ua]   + sg[ba][1][3*UPC+ua]   + bo;
                float gi = sigf(p0), gf = sigf(p1);
                float gG = tanhfast(p2), go = sigf(p3);
                cst = gf * cst + gi * gG;
                float h = go * tanhfast(cst);
                float* lp = &ubuf[q ^ 1][ba][DIN + half * UPC + ua];
                *lp = h;                                     // own recurrence
                st_dsmem(smem_u32(lp), (unsigned)peer, h);   // peer L0
                unsigned l1a = smem_u32(&ubuf[q][ba][half * UPC + ua]);
                st_dsmem(l1a, 2u, h);                        // L1a h0 region
                st_dsmem(l1a, 3u, h);                        // L1b h0 region
            }
            __syncthreads();   // B3: all stores done
            if (tid == 0) {
                mbar_arrive_rk(mb0 + (unsigned)(q ^ 1) * 8, (unsigned)peer);  // peer full
                mbar_arrive_rk(mb0 + (unsigned)q * 8, 2u);                    // L1a fullH0
                mbar_arrive_rk(mb0 + (unsigned)q * 8, 3u);                    // L1b fullH0
            }
        }
        CLUSTER_SYNC();
    } else {
        // ===================== L1 half-CTA =====================
        const int half = rank - 2;
        const unsigned peer_rk = rank ^ 1;
        {   // weights: 24/32 kb per segment in smem
            const ulonglong2* src = (const ulonglong2*)g_W1B + (size_t)half * NB1 * RPC;
            for (int e = tid; e < 2 * SKB * RPC; e += NTHR) {
                int s24 = e >> 8, rr = e & 255;
                int sseg = s24 / SKB, kbl = s24 % SKB;
                ws[e] = ldcg_u2(src + ((size_t)(sseg * NB1H + kbl) * RPC + rr));
            }
        }
        const int gr0 = half * UPC + ua;
        const float bi = b_ih1[gr0]        + b_hh1[gr0];
        const float bf = b_ih1[HH+gr0]     + b_hh1[HH+gr0];
        const float bg = b_ih1[2*HH+gr0]   + b_hh1[2*HH+gr0];
        const float bo = b_ih1[3*HH+gr0]   + b_hh1[3*HH+gr0];
        if (rank == 2) {
            if (tid < HH) swout[tid] = W_out[tid];
            if (tid == 0) sbout = b_out[0];
        }
        ubuf[0][ba][HH + ua]      = 0.0f;   // h1(-1) = 0 (both halves)
        ubuf[0][ba][HH + 64 + ua] = 0.0f;
        float cst = 0.0f;
        int phH[2] = {0, 0}, phP[2] = {0, 0};
        const ulonglong2* wsb = ws + (size_t)seg * SKB * RPC + r;
        const ulonglong2* wgb = (const ulonglong2*)g_W1B
                              + ((size_t)(half * NB1 + seg * NB1H + SKB) * RPC + r);
        __syncthreads();
        CLUSTER_SYNC();

        for (int t = 0; t < TT; ++t) {
            const int q = t & 1;
            if (tid == 0) {
                mbar_wait(mb0 + (unsigned)q * 8, (unsigned)phH[q]);           // h0(t)
                if (t > 0) mbar_wait(mb0 + 16 + (unsigned)q * 8, (unsigned)phP[q]); // peer h1(t-1)
            }
            phH[q] ^= 1;
            if (t > 0) phP[q] ^= 1;
            __syncthreads();   // B1: slot q = [h0(t) | h1(t-1)] complete

            // head: out(t-1) from h1(t-1) in slot q (rank-2 CTA only)
            if (rank == 2 && t > 0 && tid < 64) {
                int b = tid >> 3, ch = tid & 7;
                float p = 0.0f;
                #pragma unroll
                for (int m = 0; m < 16; ++m) {
                    int u = ch * 16 + m;
                    p += ubuf[q][b][HH + u] * swout[u];
                }
                p += __shfl_down_sync(0xffffffffu, p, 4, 8);
                p += __shfl_down_sync(0xffffffffu, p, 2, 8);
                p += __shfl_down_sync(0xffffffffu, p, 1, 8);
                if (ch == 0) out[(size_t)(t - 1) * BSZ + gb + b] = p + sbout;
            }

            {   // dot over slot q: smem kb + gmem tail
                unsigned long long acc[BPC];
                #pragma unroll
                for (int b = 0; b < BPC; ++b) acc[b] = 0ull;
                const float* xb = &ubuf[q][0][0];
                #pragma unroll 4
                for (int kbl = 0; kbl < SKB; ++kbl) {
                    ulonglong2 w = wsb[(size_t)kbl * RPC];
                    #pragma unroll
                    for (int b = 0; b < BPC; ++b) {
                        ulonglong2 xv =
                            ((const ulonglong2*)(xb + (size_t)b * 256))[seg * NB1H + kbl];
                        fma2(acc[b], w.x, xv.x);
                        fma2(acc[b], w.y, xv.y);
                    }
                }
                #pragma unroll
                for (int kbl = 0; kbl < GKB1; ++kbl) {
                    ulonglong2 w = ldcg_u2(wgb + (size_t)kbl * RPC);
                    #pragma unroll
                    for (int b = 0; b < BPC; ++b) {
                        ulonglong2 xv =
                            ((const ulonglong2*)(xb + (size_t)b * 256))[seg * NB1H + SKB + kbl];
                        fma2(acc[b], w.x, xv.x);
                        fma2(acc[b], w.y, xv.y);
                    }
                }
                #pragma unroll
                for (int b = 0; b < BPC; ++b)
                    sg[b][seg][r] = flo(acc[b]) + fhi(acc[b]);
            }
            __syncthreads();   // B2: slot-q reads done
            if (tid == 0) {    // release h0 slot q back to both L0 CTAs
                mbar_arrive_rk(mb0 + 16 + (unsigned)q * 8, 0u);
                mbar_arrive_rk(mb0 + 16 + (unsigned)q * 8, 1u);
            }

            {   // act
                float p0 = sg[ba][0][ua]         + sg[ba][1][ua]         + bi;
                float p1 = sg[ba][0][UPC+ua]     + sg[ba][1][UPC+ua]     + bf;
                float p2 = sg[ba][0][2*UPC+ua]   + sg[ba][1][2*UPC+ua]   + bg;
                float p3 = sg[ba][0][3*UPC+ua]   + sg[ba][1][3*UPC+ua]   + bo;
                float gi = sigf(p0), gf = sigf(p1);
                float gG = tanhfast(p2), go = sigf(p3);
                cst = gf * cst + gi * gG;
                float h = go * tanhfast(cst);
                float* lp = &ubuf[q ^ 1][ba][HH + half * UPC + ua];
                *lp = h;                                       // own recurrence
                st_dsmem(smem_u32(lp), peer_rk, h);            // peer L1
            }
            __syncthreads();   // B3
            if (tid == 0)
                mbar_arrive_rk(mb0 + 16 + (unsigned)(q ^ 1) * 8, peer_rk);
        }

        // epilogue: out(TT-1) on rank-2 (needs peer h1(TT-1) in slot 0)
        if (rank == 2) {
            if (tid == 0) mbar_wait(mb0 + 16, (unsigned)phP[0]);
            __syncthreads();
            if (tid < 64) {
                int b = tid >> 3, ch = tid & 7;
                float p = 0.0f;
                #pragma unroll
                for (int m = 0; m < 16; ++m) {
                    int u = ch * 16 + m;
                    p += ubuf[0][b][HH + u] * swout[u];
                }
                p += __shfl_down_sync(0xffffffffu, p, 4, 8);
                p += __shfl_down_sync(0xffffffffu, p, 2, 8);
                p += __shfl_down_sync(0xffffffffu, p, 1, 8);
                if (ch == 0) out[(size_t)(TT - 1) * BSZ + gb + b] = p + sbout;
            }
        }
        CLUSTER_SYNC();
    }
}

extern "C" void kernel_launch(void* const* d_in, const int* in_sizes, int n_in,
                              void* d_out, int out_size)
{
    const float* state = (const float*)d_in[0];
    const float* W_ih0 = (const float*)d_in[1];
    const float* W_hh0 = (const float*)d_in[2];
    const float* b_ih0 = (const float*)d_in[3];
    const float* b_hh0 = (const float*)d_in[4];
    const float* W_ih1 = (const float*)d_in[5];
    const float* W_hh1 = (const float*)d_in[6];
    const float* b_ih1 = (const float*)d_in[7];
    const float* b_hh1 = (const float*)d_in[8];
    const float* W_out = (const float*)d_in[9];
    const float* b_out = (const float*)d_in[10];
    float* out = (float*)d_out;

    cudaFuncSetAttribute(lstm_kernel,
                         cudaFuncAttributeMaxDynamicSharedMemorySize, DYNSMEM);
    prep_kernel<<<224, 512>>>(W_ih0, W_hh0, W_ih1, W_hh1);
    lstm_kernel<<<NCTA, NTHR, DYNSMEM>>>(state, b_ih0, b_hh0, b_ih1, b_hh1,
                                         W_out, b_out, out);
}